// round 1
// baseline (speedup 1.0000x reference)
#include <cuda_runtime.h>

#define D        128
#define DV       32          // D/4 float4 per row
#define MAXN     100000
#define CHUNK    256
#define WS_STRIDE 132        // 128 + 4 pad: conflict-free LDS.128 with interleaved cols

// 51.2 MB scratch for the aggregated messages (allocation-free per harness rules)
__device__ float g_agg[(size_t)MAXN * D];

// ---------------------------------------------------------------------------
// Kernel 1: zero the aggregation buffer
// ---------------------------------------------------------------------------
__global__ void zero_kernel(int n4) {
    int i = blockIdx.x * blockDim.x + threadIdx.x;
    if (i < n4)
        reinterpret_cast<float4*>(g_agg)[i] = make_float4(0.f, 0.f, 0.f, 0.f);
}

// ---------------------------------------------------------------------------
// Kernel 2: SpMM — warp per 256-edge chunk of the (row-sorted) edge list.
// Register-accumulate runs of equal rows; STG rows fully owned by the chunk,
// atomicAdd only rows shared with neighboring chunks.
// ---------------------------------------------------------------------------
__device__ __forceinline__ void flush_row(int row, float4 a, int lane,
                                          int first_row, bool first_shared,
                                          int last_row, bool last_shared) {
    float* p = g_agg + row * D + lane * 4;
    bool use_atomic = (row == first_row && first_shared) ||
                      (row == last_row  && last_shared);
    if (use_atomic) {
        atomicAdd(p + 0, a.x);
        atomicAdd(p + 1, a.y);
        atomicAdd(p + 2, a.z);
        atomicAdd(p + 3, a.w);
    } else {
        *reinterpret_cast<float4*>(p) = a;
    }
}

__global__ void __launch_bounds__(256) spmm_kernel(
    const int*   __restrict__ rows,
    const int*   __restrict__ cols,
    const float* __restrict__ vals,
    const float* __restrict__ h,
    int E) {
    int lane = threadIdx.x & 31;
    int warp = blockIdx.x * (blockDim.x >> 5) + (threadIdx.x >> 5);
    int start = warp * CHUNK;
    if (start >= E) return;
    int end = min(E, start + CHUNK);

    int  first_row    = __ldg(rows + start);
    int  last_row     = __ldg(rows + end - 1);
    bool first_shared = (start > 0) && (__ldg(rows + start - 1) == first_row);
    bool last_shared  = (end < E)   && (__ldg(rows + end)       == last_row);

    const float4* __restrict__ h4 = reinterpret_cast<const float4*>(h);

    float4 acc = make_float4(0.f, 0.f, 0.f, 0.f);
    int cur = first_row;

    int e = start;
    // 4-edge batches: 4 independent 512B gathers in flight per warp
    for (; e + 4 <= end; e += 4) {
        int4   r4 = *reinterpret_cast<const int4*>(rows + e);
        int4   c4 = *reinterpret_cast<const int4*>(cols + e);
        float4 v4 = *reinterpret_cast<const float4*>(vals + e);

        float4 g0 = h4[c4.x * DV + lane];
        float4 g1 = h4[c4.y * DV + lane];
        float4 g2 = h4[c4.z * DV + lane];
        float4 g3 = h4[c4.w * DV + lane];

        if (r4.x != cur) {
            flush_row(cur, acc, lane, first_row, first_shared, last_row, last_shared);
            acc = make_float4(0.f, 0.f, 0.f, 0.f); cur = r4.x;
        }
        acc.x = fmaf(v4.x, g0.x, acc.x); acc.y = fmaf(v4.x, g0.y, acc.y);
        acc.z = fmaf(v4.x, g0.z, acc.z); acc.w = fmaf(v4.x, g0.w, acc.w);

        if (r4.y != cur) {
            flush_row(cur, acc, lane, first_row, first_shared, last_row, last_shared);
            acc = make_float4(0.f, 0.f, 0.f, 0.f); cur = r4.y;
        }
        acc.x = fmaf(v4.y, g1.x, acc.x); acc.y = fmaf(v4.y, g1.y, acc.y);
        acc.z = fmaf(v4.y, g1.z, acc.z); acc.w = fmaf(v4.y, g1.w, acc.w);

        if (r4.z != cur) {
            flush_row(cur, acc, lane, first_row, first_shared, last_row, last_shared);
            acc = make_float4(0.f, 0.f, 0.f, 0.f); cur = r4.z;
        }
        acc.x = fmaf(v4.z, g2.x, acc.x); acc.y = fmaf(v4.z, g2.y, acc.y);
        acc.z = fmaf(v4.z, g2.z, acc.z); acc.w = fmaf(v4.z, g2.w, acc.w);

        if (r4.w != cur) {
            flush_row(cur, acc, lane, first_row, first_shared, last_row, last_shared);
            acc = make_float4(0.f, 0.f, 0.f, 0.f); cur = r4.w;
        }
        acc.x = fmaf(v4.w, g3.x, acc.x); acc.y = fmaf(v4.w, g3.y, acc.y);
        acc.z = fmaf(v4.w, g3.z, acc.z); acc.w = fmaf(v4.w, g3.w, acc.w);
    }
    // scalar tail (only if E % 4 != 0)
    for (; e < end; ++e) {
        int   r = __ldg(rows + e);
        int   c = __ldg(cols + e);
        float v = __ldg(vals + e);
        float4 g = h4[c * DV + lane];
        if (r != cur) {
            flush_row(cur, acc, lane, first_row, first_shared, last_row, last_shared);
            acc = make_float4(0.f, 0.f, 0.f, 0.f); cur = r;
        }
        acc.x = fmaf(v, g.x, acc.x); acc.y = fmaf(v, g.y, acc.y);
        acc.z = fmaf(v, g.z, acc.z); acc.w = fmaf(v, g.w, acc.w);
    }
    flush_row(cur, acc, lane, first_row, first_shared, last_row, last_shared);
}

// ---------------------------------------------------------------------------
// Kernel 3: out = relu(agg @ W^T + b)
// Block: 64 rows x 128 cols, 256 threads, each 4 rows x 8 cols (32 accs).
// W staged in smem [128][132] (pad -> conflict-free LDS.128), agg tile in smem.
// ---------------------------------------------------------------------------
__global__ void __launch_bounds__(256) gemm_kernel(
    const float* __restrict__ W,
    const float* __restrict__ b,
    float*       __restrict__ out,
    int n) {
    extern __shared__ float smem[];
    float* Ws = smem;                       // [128][WS_STRIDE]
    float* As = smem + 128 * WS_STRIDE;     // [64][WS_STRIDE]

    int t = threadIdx.x;

    const float4* W4 = reinterpret_cast<const float4*>(W);
    for (int idx = t; idx < 128 * 32; idx += 256) {
        int c = idx >> 5, k4 = idx & 31;
        *reinterpret_cast<float4*>(&Ws[c * WS_STRIDE + k4 * 4]) = W4[idx];
    }

    int row0 = blockIdx.x * 64;
    const float4* A4 = reinterpret_cast<const float4*>(g_agg);
    for (int idx = t; idx < 64 * 32; idx += 256) {
        int r = idx >> 5, k4 = idx & 31;
        int gr = row0 + r;
        float4 a = (gr < n) ? A4[gr * 32 + k4] : make_float4(0.f, 0.f, 0.f, 0.f);
        *reinterpret_cast<float4*>(&As[r * WS_STRIDE + k4 * 4]) = a;
    }
    __syncthreads();

    int tx = t & 15;   // col group: cols = tx + 16*j  (interleaved -> no bank conflicts)
    int ty = t >> 4;   // row group: rows = ty*4 + i

    float acc[4][8];
#pragma unroll
    for (int i = 0; i < 4; i++)
#pragma unroll
        for (int j = 0; j < 8; j++) acc[i][j] = 0.f;

    const float* Ap = As + (ty * 4) * WS_STRIDE;
    const float* Wp = Ws + tx * WS_STRIDE;

#pragma unroll 4
    for (int kk = 0; kk < 128; kk += 4) {
        float4 a[4];
        float4 w[8];
#pragma unroll
        for (int i = 0; i < 4; i++)
            a[i] = *reinterpret_cast<const float4*>(Ap + i * WS_STRIDE + kk);
#pragma unroll
        for (int j = 0; j < 8; j++)
            w[j] = *reinterpret_cast<const float4*>(Wp + j * 16 * WS_STRIDE + kk);
#pragma unroll
        for (int i = 0; i < 4; i++)
#pragma unroll
            for (int j = 0; j < 8; j++) {
                acc[i][j] = fmaf(a[i].x, w[j].x, acc[i][j]);
                acc[i][j] = fmaf(a[i].y, w[j].y, acc[i][j]);
                acc[i][j] = fmaf(a[i].z, w[j].z, acc[i][j]);
                acc[i][j] = fmaf(a[i].w, w[j].w, acc[i][j]);
            }
    }

    float bv[8];
#pragma unroll
    for (int j = 0; j < 8; j++) bv[j] = __ldg(b + tx + 16 * j);

#pragma unroll
    for (int i = 0; i < 4; i++) {
        int gr = row0 + ty * 4 + i;
        if (gr < n) {
            float* op = out + gr * D + tx;
#pragma unroll
            for (int j = 0; j < 8; j++)
                op[16 * j] = fmaxf(acc[i][j] + bv[j], 0.f);
        }
    }
}

// ---------------------------------------------------------------------------
extern "C" void kernel_launch(void* const* d_in, const int* in_sizes, int n_in,
                              void* d_out, int out_size) {
    const int*   rows = (const int*)  d_in[0];
    const int*   cols = (const int*)  d_in[1];
    const float* vals = (const float*)d_in[2];
    const float* h    = (const float*)d_in[3];
    const float* W    = (const float*)d_in[4];
    const float* b    = (const float*)d_in[5];
    float*       out  = (float*)d_out;

    int E = in_sizes[0];
    int n = in_sizes[3] / D;
    if (n > MAXN) n = MAXN;

    // 1. zero agg
    int n4 = n * DV;
    zero_kernel<<<(n4 + 255) / 256, 256>>>(n4);

    // 2. SpMM
    int warps  = (E + CHUNK - 1) / CHUNK;
    int blocks = (warps + 7) / 8;
    spmm_kernel<<<blocks, 256>>>(rows, cols, vals, h, E);

    // 3. GEMM + bias + relu
    const int smem_bytes = (128 + 64) * WS_STRIDE * sizeof(float);  // ~99 KB
    cudaFuncSetAttribute(gemm_kernel,
                         cudaFuncAttributeMaxDynamicSharedMemorySize, smem_bytes);
    gemm_kernel<<<(n + 63) / 64, 256, smem_bytes>>>(W, b, out, n);
}

// round 2
// speedup vs baseline: 1.0684x; 1.0684x over previous
#include <cuda_runtime.h>
#include <cuda_fp16.h>

#define D        128
#define DV       32          // D/4 float4 per row
#define MAXN     100000
#define CHUNK    256
#define GS       130         // Wt (transposed W) smem stride, even + pad
#define ASTR     132         // A-tile smem stride

// Scratch (allocation-free per harness rules)
__device__ __half   g_hW[(size_t)MAXN * D];   // 25.6 MB: h @ W^T in fp16
__device__ unsigned char g_flag[MAXN];        // 1 = row finalized by SpMM

// ---------------------------------------------------------------------------
// Kernel 1: zero out (atomic landing zone) + flags
// ---------------------------------------------------------------------------
__global__ void zero_kernel(float4* out4, int n4, int nflag4) {
    int i = blockIdx.x * blockDim.x + threadIdx.x;
    if (i < n4)     out4[i] = make_float4(0.f, 0.f, 0.f, 0.f);
    if (i < nflag4) reinterpret_cast<int*>(g_flag)[i] = 0;
}

// ---------------------------------------------------------------------------
// Kernel 2: hW = h @ W^T  (fp32 compute via packed FFMA2, fp16 store)
// Block: 64 rows x 128 cols, 256 threads; thread = 4 rows x 4 col-pairs.
// W staged TRANSPOSED (Wt[k][j]) so col pairs (j, j+1) are contiguous -> LDS.64
// ---------------------------------------------------------------------------
__global__ void __launch_bounds__(256) gemm_hw_kernel(
    const float* __restrict__ h,
    const float* __restrict__ W,
    int n) {
    extern __shared__ float smem[];
    float* Wt = smem;                  // [128][GS]   Wt[k][j] = W[j*128+k]
    float* As = smem + 128 * GS;       // [64][ASTR]

    int t = threadIdx.x;

    // Stage W transposed
    const float4* W4 = reinterpret_cast<const float4*>(W);
    for (int idx = t; idx < 128 * 32; idx += 256) {
        int j = idx >> 5, k4 = idx & 31;
        float4 w = W4[idx];            // W[j][4*k4 .. 4*k4+3]
        Wt[(k4 * 4 + 0) * GS + j] = w.x;
        Wt[(k4 * 4 + 1) * GS + j] = w.y;
        Wt[(k4 * 4 + 2) * GS + j] = w.z;
        Wt[(k4 * 4 + 3) * GS + j] = w.w;
    }

    // Stage A tile (64 rows of h)
    int row0 = blockIdx.x * 64;
    const float4* H4 = reinterpret_cast<const float4*>(h);
    for (int idx = t; idx < 64 * 32; idx += 256) {
        int r = idx >> 5, k4 = idx & 31;
        int gr = row0 + r;
        float4 a = (gr < n) ? H4[(size_t)gr * 32 + k4]
                            : make_float4(0.f, 0.f, 0.f, 0.f);
        *reinterpret_cast<float4*>(&As[r * ASTR + k4 * 4]) = a;
    }
    __syncthreads();

    int tx = t & 15;   // col pairs: c0 = 2*tx + 32*p, p = 0..3
    int ty = t >> 4;   // rows: ty*4 + i

    unsigned long long acc[4][4];
#pragma unroll
    for (int i = 0; i < 4; i++)
#pragma unroll
        for (int p = 0; p < 4; p++) acc[i][p] = 0ull;

    const float* Ap = As + (ty * 4) * ASTR;

#pragma unroll 4
    for (int k = 0; k < 128; k++) {
        const float* Wk = Wt + k * GS + 2 * tx;
        unsigned long long w[4];
#pragma unroll
        for (int p = 0; p < 4; p++)
            w[p] = *reinterpret_cast<const unsigned long long*>(Wk + 32 * p);
#pragma unroll
        for (int i = 0; i < 4; i++) {
            float a = Ap[i * ASTR + k];
            unsigned long long aa;
            asm("mov.b64 %0, {%1, %1};" : "=l"(aa) : "f"(a));
#pragma unroll
            for (int p = 0; p < 4; p++)
                asm("fma.rn.f32x2 %0, %1, %2, %3;"
                    : "=l"(acc[i][p]) : "l"(aa), "l"(w[p]), "l"(acc[i][p]));
        }
    }

    // Store fp16
#pragma unroll
    for (int i = 0; i < 4; i++) {
        int gr = row0 + ty * 4 + i;
        if (gr < n) {
            __half* op = g_hW + (size_t)gr * D;
#pragma unroll
            for (int p = 0; p < 4; p++) {
                float lo, hi;
                asm("mov.b64 {%0, %1}, %2;" : "=f"(lo), "=f"(hi) : "l"(acc[i][p]));
                *reinterpret_cast<__half2*>(op + 2 * tx + 32 * p) =
                    __floats2half2_rn(lo, hi);
            }
        }
    }
}

// ---------------------------------------------------------------------------
// Kernel 3: SpMM — warp per 256-edge chunk. Gathers fp16 hW rows, accumulates
// fp32. Owned rows: STG relu(acc + b) + flag. Boundary rows: atomicAdd raw.
// ---------------------------------------------------------------------------
__device__ __forceinline__ void flush_row(float* out, int row, float4 a,
                                          float4 bv, int lane,
                                          int first_row, bool first_shared,
                                          int last_row, bool last_shared) {
    float* p = out + (size_t)row * D + lane * 4;
    bool use_atomic = (row == first_row && first_shared) ||
                      (row == last_row  && last_shared);
    if (use_atomic) {
        atomicAdd(p + 0, a.x);
        atomicAdd(p + 1, a.y);
        atomicAdd(p + 2, a.z);
        atomicAdd(p + 3, a.w);
    } else {
        float4 r;
        r.x = fmaxf(a.x + bv.x, 0.f);
        r.y = fmaxf(a.y + bv.y, 0.f);
        r.z = fmaxf(a.z + bv.z, 0.f);
        r.w = fmaxf(a.w + bv.w, 0.f);
        *reinterpret_cast<float4*>(p) = r;
        if (lane == 0) g_flag[row] = 1;
    }
}

__device__ __forceinline__ float4 gather4(int c, int lane) {
    const uint2 raw = reinterpret_cast<const uint2*>(g_hW + (size_t)c * D)[lane];
    __half2 p0 = *reinterpret_cast<const __half2*>(&raw.x);
    __half2 p1 = *reinterpret_cast<const __half2*>(&raw.y);
    float2 f0 = __half22float2(p0);
    float2 f1 = __half22float2(p1);
    return make_float4(f0.x, f0.y, f1.x, f1.y);
}

__global__ void __launch_bounds__(256) spmm_kernel(
    const int*   __restrict__ rows,
    const int*   __restrict__ cols,
    const float* __restrict__ vals,
    const float* __restrict__ b,
    float*       __restrict__ out,
    int E) {
    int lane = threadIdx.x & 31;
    int warp = blockIdx.x * (blockDim.x >> 5) + (threadIdx.x >> 5);
    int start = warp * CHUNK;
    if (start >= E) return;
    int end = min(E, start + CHUNK);

    int  first_row    = __ldg(rows + start);
    int  last_row     = __ldg(rows + end - 1);
    bool first_shared = (start > 0) && (__ldg(rows + start - 1) == first_row);
    bool last_shared  = (end < E)   && (__ldg(rows + end)       == last_row);

    const float4 bv = reinterpret_cast<const float4*>(b)[lane];

    float4 acc = make_float4(0.f, 0.f, 0.f, 0.f);
    int cur = first_row;

    int e = start;
    for (; e + 4 <= end; e += 4) {
        int4   r4 = *reinterpret_cast<const int4*>(rows + e);
        int4   c4 = *reinterpret_cast<const int4*>(cols + e);
        float4 v4 = *reinterpret_cast<const float4*>(vals + e);

        float4 g0 = gather4(c4.x, lane);
        float4 g1 = gather4(c4.y, lane);
        float4 g2 = gather4(c4.z, lane);
        float4 g3 = gather4(c4.w, lane);

        if (r4.x != cur) {
            flush_row(out, cur, acc, bv, lane, first_row, first_shared, last_row, last_shared);
            acc = make_float4(0.f, 0.f, 0.f, 0.f); cur = r4.x;
        }
        acc.x = fmaf(v4.x, g0.x, acc.x); acc.y = fmaf(v4.x, g0.y, acc.y);
        acc.z = fmaf(v4.x, g0.z, acc.z); acc.w = fmaf(v4.x, g0.w, acc.w);

        if (r4.y != cur) {
            flush_row(out, cur, acc, bv, lane, first_row, first_shared, last_row, last_shared);
            acc = make_float4(0.f, 0.f, 0.f, 0.f); cur = r4.y;
        }
        acc.x = fmaf(v4.y, g1.x, acc.x); acc.y = fmaf(v4.y, g1.y, acc.y);
        acc.z = fmaf(v4.y, g1.z, acc.z); acc.w = fmaf(v4.y, g1.w, acc.w);

        if (r4.z != cur) {
            flush_row(out, cur, acc, bv, lane, first_row, first_shared, last_row, last_shared);
            acc = make_float4(0.f, 0.f, 0.f, 0.f); cur = r4.z;
        }
        acc.x = fmaf(v4.z, g2.x, acc.x); acc.y = fmaf(v4.z, g2.y, acc.y);
        acc.z = fmaf(v4.z, g2.z, acc.z); acc.w = fmaf(v4.z, g2.w, acc.w);

        if (r4.w != cur) {
            flush_row(out, cur, acc, bv, lane, first_row, first_shared, last_row, last_shared);
            acc = make_float4(0.f, 0.f, 0.f, 0.f); cur = r4.w;
        }
        acc.x = fmaf(v4.w, g3.x, acc.x); acc.y = fmaf(v4.w, g3.y, acc.y);
        acc.z = fmaf(v4.w, g3.z, acc.z); acc.w = fmaf(v4.w, g3.w, acc.w);
    }
    for (; e < end; ++e) {
        int   r = __ldg(rows + e);
        int   c = __ldg(cols + e);
        float v = __ldg(vals + e);
        float4 g = gather4(c, lane);
        if (r != cur) {
            flush_row(out, cur, acc, bv, lane, first_row, first_shared, last_row, last_shared);
            acc = make_float4(0.f, 0.f, 0.f, 0.f); cur = r;
        }
        acc.x = fmaf(v, g.x, acc.x); acc.y = fmaf(v, g.y, acc.y);
        acc.z = fmaf(v, g.z, acc.z); acc.w = fmaf(v, g.w, acc.w);
    }
    flush_row(out, cur, acc, bv, lane, first_row, first_shared, last_row, last_shared);
}

// ---------------------------------------------------------------------------
// Kernel 4: fixup — bias + relu for rows not finalized by SpMM (boundary /
// empty rows). One warp per row; ~12.5k rows do work.
// ---------------------------------------------------------------------------
__global__ void __launch_bounds__(256) fixup_kernel(
    const float* __restrict__ b,
    float*       __restrict__ out,
    int n) {
    int lane = threadIdx.x & 31;
    int row  = blockIdx.x * 8 + (threadIdx.x >> 5);
    if (row >= n) return;
    if (g_flag[row]) return;
    float4 bv = reinterpret_cast<const float4*>(b)[lane];
    float4* p = reinterpret_cast<float4*>(out + (size_t)row * D) + lane;
    float4 x = *p;
    x.x = fmaxf(x.x + bv.x, 0.f);
    x.y = fmaxf(x.y + bv.y, 0.f);
    x.z = fmaxf(x.z + bv.z, 0.f);
    x.w = fmaxf(x.w + bv.w, 0.f);
    *p = x;
}

// ---------------------------------------------------------------------------
extern "C" void kernel_launch(void* const* d_in, const int* in_sizes, int n_in,
                              void* d_out, int out_size) {
    const int*   rows = (const int*)  d_in[0];
    const int*   cols = (const int*)  d_in[1];
    const float* vals = (const float*)d_in[2];
    const float* h    = (const float*)d_in[3];
    const float* W    = (const float*)d_in[4];
    const float* b    = (const float*)d_in[5];
    float*       out  = (float*)d_out;

    int E = in_sizes[0];
    int n = in_sizes[3] / D;
    if (n > MAXN) n = MAXN;

    // 1. zero out + flags
    int n4 = n * DV;
    int nflag4 = (n + 3) / 4;
    zero_kernel<<<(n4 + 255) / 256, 256>>>((float4*)out, n4, nflag4);

    // 2. hW = h @ W^T (fp16)
    const int smem_bytes = (128 * GS + 64 * ASTR) * sizeof(float);  // ~98 KB
    cudaFuncSetAttribute(gemm_hw_kernel,
                         cudaFuncAttributeMaxDynamicSharedMemorySize, smem_bytes);
    gemm_hw_kernel<<<(n + 63) / 64, 256, smem_bytes>>>(h, W, n);

    // 3. SpMM -> out (fused bias+relu for owned rows)
    int warps  = (E + CHUNK - 1) / CHUNK;
    int blocks = (warps + 7) / 8;
    spmm_kernel<<<blocks, 256>>>(rows, cols, vals, b, out, E);

    // 4. fixup boundary/empty rows
    fixup_kernel<<<(n + 7) / 8, 256>>>(b, out, n);
}